// round 15
// baseline (speedup 1.0000x reference)
#include <cuda_runtime.h>
#include <cuda_bf16.h>
#include <cuda_fp16.h>
#include <math.h>

#define N_NODES 50000
#define N_EDGES 640000
#define DIM_IN  128
#define HC      128
#define DIM_OUT 32
#define HEADS   4
#define NEG_SLOPE 0.2f

#define SCAN_CHUNK 1024
#define SCAN_NBLK  ((N_NODES + SCAN_CHUNK - 1) / SCAN_CHUNK)   // 49

#define M_TILE   128
#define N_MTILES ((N_NODES + M_TILE - 1) / M_TILE)             // 391

typedef unsigned long long u64;
typedef unsigned int u32;

// ---------------- f32x2 helpers (node-kernel projection) --------------------
__device__ __forceinline__ u64 pack2(float lo, float hi) {
    u64 r; asm("mov.b64 %0, {%1, %2};" : "=l"(r) : "f"(lo), "f"(hi)); return r;
}
__device__ __forceinline__ void ffma2(u64& d, u64 a, u64 b) {
    asm("fma.rn.f32x2 %0, %1, %2, %3;" : "=l"(d) : "l"(a), "l"(b), "l"(d));
}
__device__ __forceinline__ float2 unpack2(u64 v) {
    float2 f; asm("mov.b64 {%0, %1}, %2;" : "=f"(f.x), "=f"(f.y) : "l"(v)); return f;
}

// ---------------- warp-MMA helpers (compute_103-safe: sm_80-era ops) --------
__device__ __forceinline__ u32 smem_u32(const void* p) {
    u32 a;
    asm("{ .reg .u64 tmp; cvta.to.shared.u64 tmp, %1; cvt.u32.u64 %0, tmp; }"
        : "=r"(a) : "l"(p));
    return a;
}
__device__ __forceinline__ void ldsm_x4(u32& r0, u32& r1, u32& r2, u32& r3, u32 addr) {
    asm volatile("ldmatrix.sync.aligned.m8n8.x4.shared.b16 {%0,%1,%2,%3}, [%4];"
                 : "=r"(r0), "=r"(r1), "=r"(r2), "=r"(r3) : "r"(addr));
}
__device__ __forceinline__ void mma_bf16(float* d, const u32* a, const u32* b) {
    asm volatile("mma.sync.aligned.m16n8k16.row.col.f32.bf16.bf16.f32 "
                 "{%0,%1,%2,%3}, {%4,%5,%6,%7}, {%8,%9}, {%0,%1,%2,%3};"
                 : "+f"(d[0]), "+f"(d[1]), "+f"(d[2]), "+f"(d[3])
                 : "r"(a[0]), "r"(a[1]), "r"(a[2]), "r"(a[3]), "r"(b[0]), "r"(b[1]));
}
// per-row 16B-chunk XOR swizzle on 256B-pitch rows
__device__ __host__ __forceinline__ u32 swz(u32 o, u32 row) {
    return o ^ ((row & 7u) << 4);
}

// ---------------- scratch (device globals: no allocation allowed) ----------
__device__ __half g_xl[(size_t)N_NODES * HC];    // 12.8 MB (fp16: gather payload)
__device__ float  g_xr[(size_t)N_NODES * HC];    // 25.6 MB
__device__ int   g_cnt[N_NODES];                 // zero-invariant between runs
__device__ int   g_off[N_NODES + 1];
__device__ int   g_woff[N_NODES];
__device__ int   g_srcs[N_EDGES];
__device__ int   g_blocksum[SCAN_NBLK];
// pre-swizzled B: [hilo][n=256 rows][k=128 bf16] = 2 x 64KB
__device__ unsigned char g_Bsw[2][65536];

// SMEM layout for mma GEMM (dynamic): A hi/lo 2x32KB, B hi/lo 2x64KB
#define SM_A     0
#define SM_B     65536
#define SM_TOTAL 196608

// ---------------- prep: transpose + split W into swizzled bf16 [n][k] ------
__global__ __launch_bounds__(256) void prepB_kernel(const float* __restrict__ Wl,
                                                    const float* __restrict__ Wr) {
    int i = blockIdx.x * 256 + threadIdx.x;
    if (i >= 256 * 64) return;
    int n  = i >> 6;          // output row (col of W): 0..255
    int kp = i & 63;          // k-pair
    int k  = kp * 2;
    const float* W = (n >= HC) ? Wr : Wl;
    int c = n & 127;
    float v0 = W[(size_t)k * HC + c];
    float v1 = W[(size_t)(k + 1) * HC + c];

    __nv_bfloat16 h0 = __float2bfloat16_rn(v0);
    __nv_bfloat16 h1 = __float2bfloat16_rn(v1);
    __nv_bfloat16 e0 = __float2bfloat16_rn(v0 - __bfloat162float(h0));
    __nv_bfloat16 e1 = __float2bfloat16_rn(v1 - __bfloat162float(h1));

    u32 so = swz((u32)(n * 256 + k * 2), (u32)n);
    *(u32*)&g_Bsw[0][so] = (u32)__bfloat16_as_ushort(h0) | ((u32)__bfloat16_as_ushort(h1) << 16);
    *(u32*)&g_Bsw[1][so] = (u32)__bfloat16_as_ushort(e0) | ((u32)__bfloat16_as_ushort(e1) << 16);
}

// ---------------- tensor-core GEMM: [xl|xr] = x @ [Wl|Wr] (R7 config) -------
__global__ __launch_bounds__(256) void gemm_tc(const float* __restrict__ x) {
    extern __shared__ unsigned char smem[];
    const u32 sbase = smem_u32(smem);
    const int t = threadIdx.x;
    const int w = t >> 5;
    const int l = t & 31;
    const int m0 = blockIdx.x * M_TILE;

    // copy pre-swizzled B (128 KB, linear)
    {
        const float4* s = (const float4*)&g_Bsw[0][0];
        float4* d4 = (float4*)(smem + SM_B);
        for (int i = t; i < 131072 / 16; i += 256) d4[i] = s[i];
    }

    // load x tile, split hi/lo bf16, store swizzled ([row][k], 256B pitch)
    for (int i = t; i < 128 * 32; i += 256) {
        int row = i >> 5;
        int k4  = i & 31;           // 4 k-values
        int node = m0 + row;
        float4 v = make_float4(0.f, 0.f, 0.f, 0.f);
        if (node < N_NODES) v = ((const float4*)x)[(size_t)node * (DIM_IN / 4) + k4];

        __nv_bfloat16 h0 = __float2bfloat16_rn(v.x);
        __nv_bfloat16 h1 = __float2bfloat16_rn(v.y);
        __nv_bfloat16 h2 = __float2bfloat16_rn(v.z);
        __nv_bfloat16 h3 = __float2bfloat16_rn(v.w);
        __nv_bfloat16 e0 = __float2bfloat16_rn(v.x - __bfloat162float(h0));
        __nv_bfloat16 e1 = __float2bfloat16_rn(v.y - __bfloat162float(h1));
        __nv_bfloat16 e2 = __float2bfloat16_rn(v.z - __bfloat162float(h2));
        __nv_bfloat16 e3 = __float2bfloat16_rn(v.w - __bfloat162float(h3));

        u64 hi = (u64)((u32)__bfloat16_as_ushort(h0) | ((u32)__bfloat16_as_ushort(h1) << 16))
               | ((u64)((u32)__bfloat16_as_ushort(h2) | ((u32)__bfloat16_as_ushort(h3) << 16)) << 32);
        u64 lo = (u64)((u32)__bfloat16_as_ushort(e0) | ((u32)__bfloat16_as_ushort(e1) << 16))
               | ((u64)((u32)__bfloat16_as_ushort(e2) | ((u32)__bfloat16_as_ushort(e3) << 16)) << 32);

        u32 so = swz((u32)(row * 256 + k4 * 8), (u32)row);
        *(u64*)(smem + SM_A + so)          = hi;
        *(u64*)(smem + SM_A + 32768 + so)  = lo;
    }
    __syncthreads();

    const int wm = w >> 2;      // 0..1
    const int wn = w & 3;       // 0..3
    const int idx8 = l & 7;
    const int g = l >> 3;       // 0..3

    float acc[4][8][4];
#pragma unroll
    for (int mf = 0; mf < 4; mf++)
#pragma unroll
        for (int nf = 0; nf < 8; nf++)
#pragma unroll
            for (int q = 0; q < 4; q++) acc[mf][nf][q] = 0.f;

#pragma unroll 1
    for (int pass = 0; pass < 3; pass++) {
        const u32 abase = sbase + SM_A + ((pass == 2) ? 32768u : 0u);
        const u32 bbase = sbase + SM_B + ((pass == 1) ? 65536u : 0u);
#pragma unroll 1
        for (int ks = 0; ks < 8; ks++) {
            u32 a[4][4];
#pragma unroll
            for (int mf = 0; mf < 4; mf++) {
                u32 row = (u32)(wm * 64 + mf * 16 + (g & 1) * 8 + idx8);
                u32 o = row * 256 + (u32)ks * 32 + (u32)(g >> 1) * 16;
                ldsm_x4(a[mf][0], a[mf][1], a[mf][2], a[mf][3], abase + swz(o, row));
            }
            u32 b[8][2];
#pragma unroll
            for (int nf2 = 0; nf2 < 4; nf2++) {
                u32 row = (u32)(wn * 64 + nf2 * 16 + (g >> 1) * 8 + idx8);
                u32 o = row * 256 + (u32)ks * 32 + (u32)(g & 1) * 16;
                u32 r0, r1, r2, r3;
                ldsm_x4(r0, r1, r2, r3, bbase + swz(o, row));
                b[2 * nf2][0] = r0;     b[2 * nf2][1] = r1;
                b[2 * nf2 + 1][0] = r2; b[2 * nf2 + 1][1] = r3;
            }
#pragma unroll
            for (int mf = 0; mf < 4; mf++)
#pragma unroll
                for (int nf = 0; nf < 8; nf++)
                    mma_bf16(acc[mf][nf], a[mf], b[nf]);
        }
    }

    // epilogue: warps wn<2 -> g_xl (fp16), wn>=2 -> g_xr (fp32)
    const int cbase = (wn & 1) * 64;
#pragma unroll
    for (int mf = 0; mf < 4; mf++) {
#pragma unroll
        for (int nf = 0; nf < 8; nf++) {
            int r0 = m0 + wm * 64 + mf * 16 + (l >> 2);
            int r1 = r0 + 8;
            int c  = cbase + nf * 8 + (l & 3) * 2;
            if (wn < 2) {
                if (r0 < N_NODES)
                    *(__half2*)(g_xl + (size_t)r0 * HC + c) =
                        __floats2half2_rn(acc[mf][nf][0], acc[mf][nf][1]);
                if (r1 < N_NODES)
                    *(__half2*)(g_xl + (size_t)r1 * HC + c) =
                        __floats2half2_rn(acc[mf][nf][2], acc[mf][nf][3]);
            } else {
                if (r0 < N_NODES)
                    *(float2*)(g_xr + (size_t)r0 * HC + c) = make_float2(acc[mf][nf][0], acc[mf][nf][1]);
                if (r1 < N_NODES)
                    *(float2*)(g_xr + (size_t)r1 * HC + c) = make_float2(acc[mf][nf][2], acc[mf][nf][3]);
            }
        }
    }
}

// ---------------- CSR build: hist(x4) -> scanA(+rezero) -> scanC -> scatter(x4)
__global__ __launch_bounds__(256) void hist_kernel(const int* __restrict__ dst) {
    int i = blockIdx.x * blockDim.x + threadIdx.x;   // i indexes edge quads
    if (i * 4 < N_EDGES) {
        int4 d4 = ((const int4*)dst)[i];             // N_EDGES % 4 == 0
        atomicAdd(&g_cnt[d4.x], 1);
        atomicAdd(&g_cnt[d4.y], 1);
        atomicAdd(&g_cnt[d4.z], 1);
        atomicAdd(&g_cnt[d4.w], 1);
    }
}

__global__ __launch_bounds__(256) void scanA_kernel() {
    __shared__ int wsum[8];
    const int t = threadIdx.x;
    const int i0 = blockIdx.x * SCAN_CHUNK + t * 4;

    int4 v = make_int4(0, 0, 0, 0);
    if (i0 < N_NODES) {
        v = *(const int4*)(g_cnt + i0);
        *(int4*)(g_cnt + i0) = make_int4(0, 0, 0, 0);   // restore zero-invariant
    }

    int e1 = v.x;
    int e2 = e1 + v.y;
    int e3 = e2 + v.z;
    int s  = e3 + v.w;

    int incl = s;
#pragma unroll
    for (int d = 1; d < 32; d <<= 1) {
        int u = __shfl_up_sync(0xffffffffu, incl, d);
        if ((t & 31) >= d) incl += u;
    }
    if ((t & 31) == 31) wsum[t >> 5] = incl;
    __syncthreads();

    if (t < 8) {
        int ws = wsum[t];
        int wincl = ws;
#pragma unroll
        for (int d = 1; d < 8; d <<= 1) {
            int u = __shfl_up_sync(0x000000ffu, wincl, d);
            if (t >= d) wincl += u;
        }
        wsum[t] = wincl - ws;
        if (t == 7) g_blocksum[blockIdx.x] = wincl;
    }
    __syncthreads();
    int wbase = wsum[t >> 5];

    const int base = wbase + (incl - s);
    if (i0 < N_NODES)
        *(int4*)(g_off + i0) = make_int4(base, base + e1, base + e2, base + e3);
}

__global__ __launch_bounds__(256) void scanC_kernel() {
    __shared__ int bs[SCAN_NBLK];
    const int t = threadIdx.x;
    if (t < SCAN_NBLK) bs[t] = g_blocksum[t];
    __syncthreads();

    int base = 0;
#pragma unroll 8
    for (int j = 0; j < SCAN_NBLK; j++)
        if (j < blockIdx.x) base += bs[j];

    const int i0 = blockIdx.x * SCAN_CHUNK + t * 4;
    if (i0 < N_NODES) {
        int4 v = *(const int4*)(g_off + i0);
        v.x += base; v.y += base; v.z += base; v.w += base;
        *(int4*)(g_off + i0)  = v;
        *(int4*)(g_woff + i0) = v;
    }
    if (blockIdx.x == 0 && t == 0) g_off[N_NODES] = N_EDGES;
}

__global__ __launch_bounds__(256) void scatter_kernel(const int* __restrict__ src,
                                                      const int* __restrict__ dst) {
    int i = blockIdx.x * blockDim.x + threadIdx.x;   // edge quads
    if (i * 4 < N_EDGES) {
        int4 d4 = ((const int4*)dst)[i];
        int4 s4 = ((const int4*)src)[i];
        int p0 = atomicAdd(&g_woff[d4.x], 1);        // 4 independent atomics (MLP=4)
        int p1 = atomicAdd(&g_woff[d4.y], 1);
        int p2 = atomicAdd(&g_woff[d4.z], 1);
        int p3 = atomicAdd(&g_woff[d4.w], 1);
        g_srcs[p0] = s4.x;
        g_srcs[p1] = s4.y;
        g_srcs[p2] = s4.z;
        g_srcs[p3] = s4.w;
    }
}

// ---------------- per-node fused attention + aggregation + projection ------
__device__ __forceinline__ float lrelu(float v) {
    return v > 0.f ? v : NEG_SLOPE * v;
}

__global__ __launch_bounds__(256, 4) void node_kernel(const float* __restrict__ att,
                                                      const float* __restrict__ bias,
                                                      const float* __restrict__ Wp,
                                                      const float* __restrict__ bp,
                                                      float* __restrict__ out) {
    __shared__ float2 Wp2[64][DIM_OUT];   // [k2][o]: (Wp[2k2][o], Wp[2k2+1][o]); 16KB
    __shared__ float sbuf[8][4][HC];      // per-warp, 4 nodes (16 KB)

    const int t = threadIdx.x;
    const int w = t >> 5;
    const int l = t & 31;

    for (int i = t; i < HC * DIM_OUT / 4; i += 256) {
        float4 v = ((const float4*)Wp)[i];
        int k = i >> 3;
        int o = (i & 7) * 4;
        float* c0 = (float*)&Wp2[k >> 1][o];
        c0[0 + (k & 1)] = v.x;
        c0[2 + (k & 1)] = v.y;
        c0[4 + (k & 1)] = v.z;
        c0[6 + (k & 1)] = v.w;
    }
    __syncthreads();

    const int half = l >> 4;      // which edge of a pair
    const int q    = l & 15;      // feature octet

    float a8[8], b8[8];
    *(float4*)&a8[0] = *(const float4*)(att + 8 * q);
    *(float4*)&a8[4] = *(const float4*)(att + 8 * q + 4);
    *(float4*)&b8[0] = *(const float4*)(bias + 8 * q);
    *(float4*)&b8[4] = *(const float4*)(bias + 8 * q + 4);
    const float bpl = bp[l];
    const int wg = blockIdx.x * 8 + w;

    // ---- phase 1: aggregation for up to 4 nodes, results into sbuf -------
#pragma unroll 1
    for (int nn = 0; nn < 4; nn++) {
        const int node = wg * 4 + nn;
        if (node >= N_NODES) break;

        float xr8[8];
        *(float4*)&xr8[0] = *(const float4*)(g_xr + (size_t)node * HC + 8 * q);
        *(float4*)&xr8[4] = *(const float4*)(g_xr + (size_t)node * HC + 8 * q + 4);

        const int e0 = g_off[node];
        const int e1 = g_off[node + 1];

        float denom = 0.f;
        float acc[8];
#pragma unroll
        for (int i = 0; i < 8; i++) acc[i] = 0.f;

        for (int base = e0; base < e1; base += 32) {
            const int nE = min(32, e1 - base);
            int sv = (l < nE) ? g_srcs[base + l] : 0;

            for (int j = 0; j < nE; j += 4) {
                const int i0 = j + half;
                const int i1 = j + 2 + half;
                const int s0 = __shfl_sync(0xffffffffu, sv, i0 & 31);
                const int s1 = __shfl_sync(0xffffffffu, sv, i1 & 31);
                const bool v0 = i0 < nE;
                const bool v1 = i1 < nE;

                const uint4 u0 = *(const uint4*)(g_xl + (size_t)s0 * HC + 8 * q);
                uint4 u1 = make_uint4(0, 0, 0, 0);
                if (v1) u1 = *(const uint4*)(g_xl + (size_t)s1 * HC + 8 * q);

                float x0[8], x1[8];
                {
                    float2 f;
                    f = __half22float2(*(const __half2*)&u0.x); x0[0] = f.x; x0[1] = f.y;
                    f = __half22float2(*(const __half2*)&u0.y); x0[2] = f.x; x0[3] = f.y;
                    f = __half22float2(*(const __half2*)&u0.z); x0[4] = f.x; x0[5] = f.y;
                    f = __half22float2(*(const __half2*)&u0.w); x0[6] = f.x; x0[7] = f.y;
                    f = __half22float2(*(const __half2*)&u1.x); x1[0] = f.x; x1[1] = f.y;
                    f = __half22float2(*(const __half2*)&u1.y); x1[2] = f.x; x1[3] = f.y;
                    f = __half22float2(*(const __half2*)&u1.z); x1[4] = f.x; x1[5] = f.y;
                    f = __half22float2(*(const __half2*)&u1.w); x1[6] = f.x; x1[7] = f.y;
                }

                float p0 = 0.f, p1 = 0.f;
#pragma unroll
                for (int i = 0; i < 8; i++) {
                    p0 += a8[i] * lrelu(x0[i] + xr8[i]);
                    p1 += a8[i] * lrelu(x1[i] + xr8[i]);
                }
                p0 += __shfl_xor_sync(0xffffffffu, p0, 1);
                p1 += __shfl_xor_sync(0xffffffffu, p1, 1);
                p0 += __shfl_xor_sync(0xffffffffu, p0, 2);
                p1 += __shfl_xor_sync(0xffffffffu, p1, 2);

                const float ev0 = v0 ? __expf(p0) : 0.f;
                const float ev1 = v1 ? __expf(p1) : 0.f;
                denom += ev0 + ev1;
#pragma unroll
                for (int i = 0; i < 8; i++)
                    acc[i] += x0[i] * ev0 + x1[i] * ev1;
            }
        }

        denom += __shfl_xor_sync(0xffffffffu, denom, 16);
#pragma unroll
        for (int i = 0; i < 8; i++)
            acc[i] += __shfl_xor_sync(0xffffffffu, acc[i], 16);

        const float inv = 1.f / (denom + 1e-16f);
        if (half == 0) {
#pragma unroll
            for (int i = 0; i < 8; i++)
                sbuf[w][nn][8 * q + i] = acc[i] * inv + b8[i];
        }
    }
    __syncwarp();

    // ---- phase 2: batched projection, lane l -> output col l -------------
    {
        const u64* wp = (const u64*)&Wp2[0][0];   // index: k2*32 + l (conflict-free)
        const u64* sp0 = (const u64*)&sbuf[w][0][0];
        const u64* sp1 = (const u64*)&sbuf[w][1][0];
        const u64* sp2 = (const u64*)&sbuf[w][2][0];
        const u64* sp3 = (const u64*)&sbuf[w][3][0];
        u64 r0 = pack2(bpl, 0.f), r1 = r0, r2 = r0, r3 = r0;
#pragma unroll 8
        for (int k2 = 0; k2 < HC / 2; k2++) {
            const u64 wv = wp[k2 * DIM_OUT + l];   // one read serves 4 nodes
            ffma2(r0, sp0[k2], wv);
            ffma2(r1, sp1[k2], wv);
            ffma2(r2, sp2[k2], wv);
            ffma2(r3, sp3[k2], wv);
        }
        const int n0 = wg * 4;
        float2 f;
        if (n0 + 0 < N_NODES) { f = unpack2(r0); out[(size_t)(n0 + 0) * DIM_OUT + l] = f.x + f.y; }
        if (n0 + 1 < N_NODES) { f = unpack2(r1); out[(size_t)(n0 + 1) * DIM_OUT + l] = f.x + f.y; }
        if (n0 + 2 < N_NODES) { f = unpack2(r2); out[(size_t)(n0 + 2) * DIM_OUT + l] = f.x + f.y; }
        if (n0 + 3 < N_NODES) { f = unpack2(r3); out[(size_t)(n0 + 3) * DIM_OUT + l] = f.x + f.y; }
    }
}

// ---------------- launch: two-stream fork/join inside the captured graph ----
extern "C" void kernel_launch(void* const* d_in, const int* in_sizes, int n_in,
                              void* d_out, int out_size) {
    const float* x    = (const float*)d_in[0];
    const int*   ei   = (const int*)d_in[1];
    const float* Wl   = (const float*)d_in[2];
    const float* Wr   = (const float*)d_in[3];
    const float* att  = (const float*)d_in[4];
    const float* bias = (const float*)d_in[5];
    const float* Wp   = (const float*)d_in[6];
    const float* bp   = (const float*)d_in[7];
    const int* src = ei;
    const int* dst = ei + N_EDGES;

    cudaFuncSetAttribute(gemm_tc, cudaFuncAttributeMaxDynamicSharedMemorySize, SM_TOTAL);

    // lazily created, reused every call (no device memory involved)
    static cudaStream_t s1 = nullptr;
    static cudaEvent_t evFork = nullptr, evJoin = nullptr;
    if (s1 == nullptr) {
        cudaStreamCreateWithFlags(&s1, cudaStreamNonBlocking);
        cudaEventCreateWithFlags(&evFork, cudaEventDisableTiming);
        cudaEventCreateWithFlags(&evJoin, cudaEventDisableTiming);
    }

    // fork: CSR-build branch on s1 (4 kernels; g_cnt zero-invariant)
    cudaEventRecord(evFork, 0);
    cudaStreamWaitEvent(s1, evFork, 0);
    hist_kernel<<<(N_EDGES / 4 + 255) / 256, 256, 0, s1>>>(dst);
    scanA_kernel<<<SCAN_NBLK, 256, 0, s1>>>();
    scanC_kernel<<<SCAN_NBLK, 256, 0, s1>>>();
    scatter_kernel<<<(N_EDGES / 4 + 255) / 256, 256, 0, s1>>>(src, dst);
    cudaEventRecord(evJoin, s1);

    // main branch: GEMM
    prepB_kernel<<<64, 256>>>(Wl, Wr);
    gemm_tc<<<N_MTILES, 256, SM_TOTAL>>>(x);

    // join, then the fused node phase
    cudaStreamWaitEvent(0, evJoin, 0);
    node_kernel<<<(N_NODES + 31) / 32, 256>>>(att, bias, Wp, bp, (float*)d_out);
}

// round 16
// speedup vs baseline: 1.0206x; 1.0206x over previous
#include <cuda_runtime.h>
#include <cuda_bf16.h>
#include <cuda_fp16.h>
#include <math.h>

#define N_NODES 50000
#define N_EDGES 640000
#define DIM_IN  128
#define HC      128
#define DIM_OUT 32
#define HEADS   4
#define NEG_SLOPE 0.2f

#define SCAN_CHUNK 1024
#define SCAN_NBLK  ((N_NODES + SCAN_CHUNK - 1) / SCAN_CHUNK)   // 49

#define M_TILE   128
#define N_MTILES ((N_NODES + M_TILE - 1) / M_TILE)             // 391

typedef unsigned long long u64;
typedef unsigned int u32;

// ---------------- f32x2 helpers (node-kernel projection) --------------------
__device__ __forceinline__ u64 pack2(float lo, float hi) {
    u64 r; asm("mov.b64 %0, {%1, %2};" : "=l"(r) : "f"(lo), "f"(hi)); return r;
}
__device__ __forceinline__ void ffma2(u64& d, u64 a, u64 b) {
    asm("fma.rn.f32x2 %0, %1, %2, %3;" : "=l"(d) : "l"(a), "l"(b), "l"(d));
}
__device__ __forceinline__ float2 unpack2(u64 v) {
    float2 f; asm("mov.b64 {%0, %1}, %2;" : "=f"(f.x), "=f"(f.y) : "l"(v)); return f;
}

// ---------------- warp-MMA helpers (compute_103-safe: sm_80-era ops) --------
__device__ __forceinline__ u32 smem_u32(const void* p) {
    u32 a;
    asm("{ .reg .u64 tmp; cvta.to.shared.u64 tmp, %1; cvt.u32.u64 %0, tmp; }"
        : "=r"(a) : "l"(p));
    return a;
}
__device__ __forceinline__ void ldsm_x4(u32& r0, u32& r1, u32& r2, u32& r3, u32 addr) {
    asm volatile("ldmatrix.sync.aligned.m8n8.x4.shared.b16 {%0,%1,%2,%3}, [%4];"
                 : "=r"(r0), "=r"(r1), "=r"(r2), "=r"(r3) : "r"(addr));
}
__device__ __forceinline__ void mma_bf16(float* d, const u32* a, const u32* b) {
    asm volatile("mma.sync.aligned.m16n8k16.row.col.f32.bf16.bf16.f32 "
                 "{%0,%1,%2,%3}, {%4,%5,%6,%7}, {%8,%9}, {%0,%1,%2,%3};"
                 : "+f"(d[0]), "+f"(d[1]), "+f"(d[2]), "+f"(d[3])
                 : "r"(a[0]), "r"(a[1]), "r"(a[2]), "r"(a[3]), "r"(b[0]), "r"(b[1]));
}
// per-row 16B-chunk XOR swizzle on 256B-pitch rows
__device__ __host__ __forceinline__ u32 swz(u32 o, u32 row) {
    return o ^ ((row & 7u) << 4);
}

// ---------------- scratch (device globals: no allocation allowed) ----------
__device__ __half g_xl[(size_t)N_NODES * HC];    // 12.8 MB (fp16: gather payload)
__device__ float  g_xr[(size_t)N_NODES * HC];    // 25.6 MB
__device__ int   g_cnt[N_NODES];                 // zero-invariant between runs
__device__ int   g_off[N_NODES + 1];
__device__ int   g_woff[N_NODES];
__device__ int   g_srcs[N_EDGES];
__device__ int   g_blocksum[SCAN_NBLK];
// pre-swizzled B: [hilo][n=256 rows][k=128 bf16] = 2 x 64KB
__device__ unsigned char g_Bsw[2][65536];

// SMEM layout for mma GEMM (dynamic): A hi/lo 2x32KB, B hi/lo 2x64KB
#define SM_A     0
#define SM_B     65536
#define SM_TOTAL 196608

// ---------------- prep: transpose + split W into swizzled bf16 [n][k] ------
__global__ __launch_bounds__(256) void prepB_kernel(const float* __restrict__ Wl,
                                                    const float* __restrict__ Wr) {
    int i = blockIdx.x * 256 + threadIdx.x;
    if (i >= 256 * 64) return;
    int n  = i >> 6;          // output row (col of W): 0..255
    int kp = i & 63;          // k-pair
    int k  = kp * 2;
    const float* W = (n >= HC) ? Wr : Wl;
    int c = n & 127;
    float v0 = W[(size_t)k * HC + c];
    float v1 = W[(size_t)(k + 1) * HC + c];

    __nv_bfloat16 h0 = __float2bfloat16_rn(v0);
    __nv_bfloat16 h1 = __float2bfloat16_rn(v1);
    __nv_bfloat16 e0 = __float2bfloat16_rn(v0 - __bfloat162float(h0));
    __nv_bfloat16 e1 = __float2bfloat16_rn(v1 - __bfloat162float(h1));

    u32 so = swz((u32)(n * 256 + k * 2), (u32)n);
    *(u32*)&g_Bsw[0][so] = (u32)__bfloat16_as_ushort(h0) | ((u32)__bfloat16_as_ushort(h1) << 16);
    *(u32*)&g_Bsw[1][so] = (u32)__bfloat16_as_ushort(e0) | ((u32)__bfloat16_as_ushort(e1) << 16);
}

// ---------------- tensor-core GEMM: [xl|xr] = x @ [Wl|Wr] (R7 config) -------
__global__ __launch_bounds__(256) void gemm_tc(const float* __restrict__ x) {
    extern __shared__ unsigned char smem[];
    const u32 sbase = smem_u32(smem);
    const int t = threadIdx.x;
    const int w = t >> 5;
    const int l = t & 31;
    const int m0 = blockIdx.x * M_TILE;

    // copy pre-swizzled B (128 KB, linear)
    {
        const float4* s = (const float4*)&g_Bsw[0][0];
        float4* d4 = (float4*)(smem + SM_B);
        for (int i = t; i < 131072 / 16; i += 256) d4[i] = s[i];
    }

    // load x tile, split hi/lo bf16, store swizzled ([row][k], 256B pitch)
    for (int i = t; i < 128 * 32; i += 256) {
        int row = i >> 5;
        int k4  = i & 31;           // 4 k-values
        int node = m0 + row;
        float4 v = make_float4(0.f, 0.f, 0.f, 0.f);
        if (node < N_NODES) v = ((const float4*)x)[(size_t)node * (DIM_IN / 4) + k4];

        __nv_bfloat16 h0 = __float2bfloat16_rn(v.x);
        __nv_bfloat16 h1 = __float2bfloat16_rn(v.y);
        __nv_bfloat16 h2 = __float2bfloat16_rn(v.z);
        __nv_bfloat16 h3 = __float2bfloat16_rn(v.w);
        __nv_bfloat16 e0 = __float2bfloat16_rn(v.x - __bfloat162float(h0));
        __nv_bfloat16 e1 = __float2bfloat16_rn(v.y - __bfloat162float(h1));
        __nv_bfloat16 e2 = __float2bfloat16_rn(v.z - __bfloat162float(h2));
        __nv_bfloat16 e3 = __float2bfloat16_rn(v.w - __bfloat162float(h3));

        u64 hi = (u64)((u32)__bfloat16_as_ushort(h0) | ((u32)__bfloat16_as_ushort(h1) << 16))
               | ((u64)((u32)__bfloat16_as_ushort(h2) | ((u32)__bfloat16_as_ushort(h3) << 16)) << 32);
        u64 lo = (u64)((u32)__bfloat16_as_ushort(e0) | ((u32)__bfloat16_as_ushort(e1) << 16))
               | ((u64)((u32)__bfloat16_as_ushort(e2) | ((u32)__bfloat16_as_ushort(e3) << 16)) << 32);

        u32 so = swz((u32)(row * 256 + k4 * 8), (u32)row);
        *(u64*)(smem + SM_A + so)          = hi;
        *(u64*)(smem + SM_A + 32768 + so)  = lo;
    }
    __syncthreads();

    const int wm = w >> 2;      // 0..1
    const int wn = w & 3;       // 0..3
    const int idx8 = l & 7;
    const int g = l >> 3;       // 0..3

    float acc[4][8][4];
#pragma unroll
    for (int mf = 0; mf < 4; mf++)
#pragma unroll
        for (int nf = 0; nf < 8; nf++)
#pragma unroll
            for (int q = 0; q < 4; q++) acc[mf][nf][q] = 0.f;

#pragma unroll 1
    for (int pass = 0; pass < 3; pass++) {
        const u32 abase = sbase + SM_A + ((pass == 2) ? 32768u : 0u);
        const u32 bbase = sbase + SM_B + ((pass == 1) ? 65536u : 0u);
#pragma unroll 1
        for (int ks = 0; ks < 8; ks++) {
            u32 a[4][4];
#pragma unroll
            for (int mf = 0; mf < 4; mf++) {
                u32 row = (u32)(wm * 64 + mf * 16 + (g & 1) * 8 + idx8);
                u32 o = row * 256 + (u32)ks * 32 + (u32)(g >> 1) * 16;
                ldsm_x4(a[mf][0], a[mf][1], a[mf][2], a[mf][3], abase + swz(o, row));
            }
            u32 b[8][2];
#pragma unroll
            for (int nf2 = 0; nf2 < 4; nf2++) {
                u32 row = (u32)(wn * 64 + nf2 * 16 + (g >> 1) * 8 + idx8);
                u32 o = row * 256 + (u32)ks * 32 + (u32)(g & 1) * 16;
                u32 r0, r1, r2, r3;
                ldsm_x4(r0, r1, r2, r3, bbase + swz(o, row));
                b[2 * nf2][0] = r0;     b[2 * nf2][1] = r1;
                b[2 * nf2 + 1][0] = r2; b[2 * nf2 + 1][1] = r3;
            }
#pragma unroll
            for (int mf = 0; mf < 4; mf++)
#pragma unroll
                for (int nf = 0; nf < 8; nf++)
                    mma_bf16(acc[mf][nf], a[mf], b[nf]);
        }
    }

    // epilogue: warps wn<2 -> g_xl (fp16), wn>=2 -> g_xr (fp32)
    const int cbase = (wn & 1) * 64;
#pragma unroll
    for (int mf = 0; mf < 4; mf++) {
#pragma unroll
        for (int nf = 0; nf < 8; nf++) {
            int r0 = m0 + wm * 64 + mf * 16 + (l >> 2);
            int r1 = r0 + 8;
            int c  = cbase + nf * 8 + (l & 3) * 2;
            if (wn < 2) {
                if (r0 < N_NODES)
                    *(__half2*)(g_xl + (size_t)r0 * HC + c) =
                        __floats2half2_rn(acc[mf][nf][0], acc[mf][nf][1]);
                if (r1 < N_NODES)
                    *(__half2*)(g_xl + (size_t)r1 * HC + c) =
                        __floats2half2_rn(acc[mf][nf][2], acc[mf][nf][3]);
            } else {
                if (r0 < N_NODES)
                    *(float2*)(g_xr + (size_t)r0 * HC + c) = make_float2(acc[mf][nf][0], acc[mf][nf][1]);
                if (r1 < N_NODES)
                    *(float2*)(g_xr + (size_t)r1 * HC + c) = make_float2(acc[mf][nf][2], acc[mf][nf][3]);
            }
        }
    }
}

// ---------------- CSR build: hist(x4) -> scanA(+rezero) -> scanC -> scatter -
__global__ __launch_bounds__(256) void hist_kernel(const int* __restrict__ dst) {
    int i = blockIdx.x * blockDim.x + threadIdx.x;   // edge quads
    if (i * 4 < N_EDGES) {
        int4 d4 = ((const int4*)dst)[i];             // N_EDGES % 4 == 0
        atomicAdd(&g_cnt[d4.x], 1);
        atomicAdd(&g_cnt[d4.y], 1);
        atomicAdd(&g_cnt[d4.z], 1);
        atomicAdd(&g_cnt[d4.w], 1);
    }
}

__global__ __launch_bounds__(256) void scanA_kernel() {
    __shared__ int wsum[8];
    const int t = threadIdx.x;
    const int i0 = blockIdx.x * SCAN_CHUNK + t * 4;

    int4 v = make_int4(0, 0, 0, 0);
    if (i0 < N_NODES) {
        v = *(const int4*)(g_cnt + i0);
        *(int4*)(g_cnt + i0) = make_int4(0, 0, 0, 0);   // restore zero-invariant
    }

    int e1 = v.x;
    int e2 = e1 + v.y;
    int e3 = e2 + v.z;
    int s  = e3 + v.w;

    int incl = s;
#pragma unroll
    for (int d = 1; d < 32; d <<= 1) {
        int u = __shfl_up_sync(0xffffffffu, incl, d);
        if ((t & 31) >= d) incl += u;
    }
    if ((t & 31) == 31) wsum[t >> 5] = incl;
    __syncthreads();

    if (t < 8) {
        int ws = wsum[t];
        int wincl = ws;
#pragma unroll
        for (int d = 1; d < 8; d <<= 1) {
            int u = __shfl_up_sync(0x000000ffu, wincl, d);
            if (t >= d) wincl += u;
        }
        wsum[t] = wincl - ws;
        if (t == 7) g_blocksum[blockIdx.x] = wincl;
    }
    __syncthreads();
    int wbase = wsum[t >> 5];

    const int base = wbase + (incl - s);
    if (i0 < N_NODES)
        *(int4*)(g_off + i0) = make_int4(base, base + e1, base + e2, base + e3);
}

__global__ __launch_bounds__(256) void scanC_kernel() {
    __shared__ int bs[SCAN_NBLK];
    const int t = threadIdx.x;
    if (t < SCAN_NBLK) bs[t] = g_blocksum[t];
    __syncthreads();

    int base = 0;
#pragma unroll 8
    for (int j = 0; j < SCAN_NBLK; j++)
        if (j < blockIdx.x) base += bs[j];

    const int i0 = blockIdx.x * SCAN_CHUNK + t * 4;
    if (i0 < N_NODES) {
        int4 v = *(const int4*)(g_off + i0);
        v.x += base; v.y += base; v.z += base; v.w += base;
        *(int4*)(g_off + i0)  = v;
        *(int4*)(g_woff + i0) = v;
    }
    if (blockIdx.x == 0 && t == 0) g_off[N_NODES] = N_EDGES;
}

__global__ void scatter_kernel(const int* __restrict__ src, const int* __restrict__ dst) {
    int e = blockIdx.x * blockDim.x + threadIdx.x;
    if (e < N_EDGES) {
        int d = dst[e];
        int p = atomicAdd(&g_woff[d], 1);
        g_srcs[p] = src[e];
    }
}

// ---------------- per-node fused attention + aggregation + projection ------
// 16 lanes per edge, 2 edges per warp in flight.
// logit uses a.lrelu(z) = 0.6*(a.z) + 0.4*(a.|z|): two FFMA chains, |z| as
// free SASS operand modifier -> ~20% fewer logit ops than sel-based lrelu.
__global__ __launch_bounds__(256, 4) void node_kernel(const float* __restrict__ att,
                                                      const float* __restrict__ bias,
                                                      const float* __restrict__ Wp,
                                                      const float* __restrict__ bp,
                                                      float* __restrict__ out) {
    __shared__ float2 Wp2[64][DIM_OUT];   // [k2][o]: (Wp[2k2][o], Wp[2k2+1][o]); 16KB
    __shared__ float sbuf[8][4][HC];      // per-warp, 4 nodes (16 KB)

    const int t = threadIdx.x;
    const int w = t >> 5;
    const int l = t & 31;

    for (int i = t; i < HC * DIM_OUT / 4; i += 256) {
        float4 v = ((const float4*)Wp)[i];
        int k = i >> 3;
        int o = (i & 7) * 4;
        float* c0 = (float*)&Wp2[k >> 1][o];
        c0[0 + (k & 1)] = v.x;
        c0[2 + (k & 1)] = v.y;
        c0[4 + (k & 1)] = v.z;
        c0[6 + (k & 1)] = v.w;
    }
    __syncthreads();

    const int half = l >> 4;      // which edge of a pair
    const int q    = l & 15;      // feature octet

    float a8[8], b8[8];
    *(float4*)&a8[0] = *(const float4*)(att + 8 * q);
    *(float4*)&a8[4] = *(const float4*)(att + 8 * q + 4);
    *(float4*)&b8[0] = *(const float4*)(bias + 8 * q);
    *(float4*)&b8[4] = *(const float4*)(bias + 8 * q + 4);
    const float bpl = bp[l];
    const int wg = blockIdx.x * 8 + w;

    // ---- phase 1: aggregation for up to 4 nodes, results into sbuf -------
#pragma unroll 1
    for (int nn = 0; nn < 4; nn++) {
        const int node = wg * 4 + nn;
        if (node >= N_NODES) break;

        float xr8[8];
        *(float4*)&xr8[0] = *(const float4*)(g_xr + (size_t)node * HC + 8 * q);
        *(float4*)&xr8[4] = *(const float4*)(g_xr + (size_t)node * HC + 8 * q + 4);

        const int e0 = g_off[node];
        const int e1 = g_off[node + 1];

        float denom = 0.f;
        float acc[8];
#pragma unroll
        for (int i = 0; i < 8; i++) acc[i] = 0.f;

        for (int base = e0; base < e1; base += 32) {
            const int nE = min(32, e1 - base);
            int sv = (l < nE) ? g_srcs[base + l] : 0;

            for (int j = 0; j < nE; j += 4) {
                const int i0 = j + half;
                const int i1 = j + 2 + half;
                const int s0 = __shfl_sync(0xffffffffu, sv, i0 & 31);
                const int s1 = __shfl_sync(0xffffffffu, sv, i1 & 31);
                const bool v0 = i0 < nE;
                const bool v1 = i1 < nE;

                // unconditional gathers (masked indices are valid rows;
                // validity enforced via ev gating below)
                const uint4 u0 = *(const uint4*)(g_xl + (size_t)s0 * HC + 8 * q);
                const uint4 u1 = *(const uint4*)(g_xl + (size_t)s1 * HC + 8 * q);

                float x0[8], x1[8];
                {
                    float2 f;
                    f = __half22float2(*(const __half2*)&u0.x); x0[0] = f.x; x0[1] = f.y;
                    f = __half22float2(*(const __half2*)&u0.y); x0[2] = f.x; x0[3] = f.y;
                    f = __half22float2(*(const __half2*)&u0.z); x0[4] = f.x; x0[5] = f.y;
                    f = __half22float2(*(const __half2*)&u0.w); x0[6] = f.x; x0[7] = f.y;
                    f = __half22float2(*(const __half2*)&u1.x); x1[0] = f.x; x1[1] = f.y;
                    f = __half22float2(*(const __half2*)&u1.y); x1[2] = f.x; x1[3] = f.y;
                    f = __half22float2(*(const __half2*)&u1.z); x1[4] = f.x; x1[5] = f.y;
                    f = __half22float2(*(const __half2*)&u1.w); x1[6] = f.x; x1[7] = f.y;
                }

                // a . lrelu(z) via 0.6*(a.z) + 0.4*(a.|z|)
                float s0p = 0.f, t0p = 0.f, s1p = 0.f, t1p = 0.f;
#pragma unroll
                for (int i = 0; i < 8; i++) {
                    float z0 = x0[i] + xr8[i];
                    float z1 = x1[i] + xr8[i];
                    s0p = fmaf(a8[i], z0, s0p);
                    t0p = fmaf(a8[i], fabsf(z0), t0p);
                    s1p = fmaf(a8[i], z1, s1p);
                    t1p = fmaf(a8[i], fabsf(z1), t1p);
                }
                float p0 = 0.6f * s0p + 0.4f * t0p;
                float p1 = 0.6f * s1p + 0.4f * t1p;

                p0 += __shfl_xor_sync(0xffffffffu, p0, 1);
                p1 += __shfl_xor_sync(0xffffffffu, p1, 1);
                p0 += __shfl_xor_sync(0xffffffffu, p0, 2);
                p1 += __shfl_xor_sync(0xffffffffu, p1, 2);

                const float ev0 = v0 ? __expf(p0) : 0.f;
                const float ev1 = v1 ? __expf(p1) : 0.f;
                denom += ev0 + ev1;
#pragma unroll
                for (int i = 0; i < 8; i++)
                    acc[i] += x0[i] * ev0 + x1[i] * ev1;
            }
        }

        denom += __shfl_xor_sync(0xffffffffu, denom, 16);
#pragma unroll
        for (int i = 0; i < 8; i++)
            acc[i] += __shfl_xor_sync(0xffffffffu, acc[i], 16);

        const float inv = 1.f / (denom + 1e-16f);
        if (half == 0) {
#pragma unroll
            for (int i = 0; i < 8; i++)
                sbuf[w][nn][8 * q + i] = acc[i] * inv + b8[i];
        }
    }
    __syncwarp();

    // ---- phase 2: batched projection, lane l -> output col l -------------
    {
        const u64* wp = (const u64*)&Wp2[0][0];   // index: k2*32 + l (conflict-free)
        const u64* sp0 = (const u64*)&sbuf[w][0][0];
        const u64* sp1 = (const u64*)&sbuf[w][1][0];
        const u64* sp2 = (const u64*)&sbuf[w][2][0];
        const u64* sp3 = (const u64*)&sbuf[w][3][0];
        u64 r0 = pack2(bpl, 0.f), r1 = r0, r2 = r0, r3 = r0;
#pragma unroll 8
        for (int k2 = 0; k2 < HC / 2; k2++) {
            const u64 wv = wp[k2 * DIM_OUT + l];   // one read serves 4 nodes
            ffma2(r0, sp0[k2], wv);
            ffma2(r1, sp1[k2], wv);
            ffma2(r2, sp2[k2], wv);
            ffma2(r3, sp3[k2], wv);
        }
        const int n0 = wg * 4;
        float2 f;
        if (n0 + 0 < N_NODES) { f = unpack2(r0); out[(size_t)(n0 + 0) * DIM_OUT + l] = f.x + f.y; }
        if (n0 + 1 < N_NODES) { f = unpack2(r1); out[(size_t)(n0 + 1) * DIM_OUT + l] = f.x + f.y; }
        if (n0 + 2 < N_NODES) { f = unpack2(r2); out[(size_t)(n0 + 2) * DIM_OUT + l] = f.x + f.y; }
        if (n0 + 3 < N_NODES) { f = unpack2(r3); out[(size_t)(n0 + 3) * DIM_OUT + l] = f.x + f.y; }
    }
}

// ---------------- launch: two-stream fork/join inside the captured graph ----
extern "C" void kernel_launch(void* const* d_in, const int* in_sizes, int n_in,
                              void* d_out, int out_size) {
    const float* x    = (const float*)d_in[0];
    const int*   ei   = (const int*)d_in[1];
    const float* Wl   = (const float*)d_in[2];
    const float* Wr   = (const float*)d_in[3];
    const float* att  = (const float*)d_in[4];
    const float* bias = (const float*)d_in[5];
    const float* Wp   = (const float*)d_in[6];
    const float* bp   = (const float*)d_in[7];
    const int* src = ei;
    const int* dst = ei + N_EDGES;

    cudaFuncSetAttribute(gemm_tc, cudaFuncAttributeMaxDynamicSharedMemorySize, SM_TOTAL);

    // lazily created, reused every call (no device memory involved)
    static cudaStream_t s1 = nullptr;
    static cudaEvent_t evFork = nullptr, evJoin = nullptr;
    if (s1 == nullptr) {
        cudaStreamCreateWithFlags(&s1, cudaStreamNonBlocking);
        cudaEventCreateWithFlags(&evFork, cudaEventDisableTiming);
        cudaEventCreateWithFlags(&evJoin, cudaEventDisableTiming);
    }

    // fork: CSR-build branch on s1 (4 kernels; g_cnt zero-invariant)
    cudaEventRecord(evFork, 0);
    cudaStreamWaitEvent(s1, evFork, 0);
    hist_kernel<<<(N_EDGES / 4 + 255) / 256, 256, 0, s1>>>(dst);
    scanA_kernel<<<SCAN_NBLK, 256, 0, s1>>>();
    scanC_kernel<<<SCAN_NBLK, 256, 0, s1>>>();
    scatter_kernel<<<(N_EDGES + 255) / 256, 256, 0, s1>>>(src, dst);
    cudaEventRecord(evJoin, s1);

    // main branch: GEMM
    prepB_kernel<<<64, 256>>>(Wl, Wr);
    gemm_tc<<<N_MTILES, 256, SM_TOTAL>>>(x);

    // join, then the fused node phase
    cudaStreamWaitEvent(0, evJoin, 0);
    node_kernel<<<(N_NODES + 31) / 32, 256>>>(att, bias, Wp, bp, (float*)d_out);
}